// round 3
// baseline (speedup 1.0000x reference)
#include <cuda_runtime.h>
#include <cuda_fp16.h>
#include <cstdint>

#define Bz 4
#define S 1024
#define D 768
#define H 12
#define DK 64
#define BH (Bz*H)

// ---------------- scratch (device globals) ----------------
__device__ float g_Q[Bz*S*D];
__device__ float g_K[Bz*S*D];
__device__ float g_QT[BH*DK*S];
__device__ float g_KT[BH*DK*S];
__device__ __half g_P[(size_t)BH*S*S];      // P = exp(score) (0 where masked), layout [bh][t][s]
__device__ float g_ctx[2*Bz*S*D];           // ctx1 | ctx2 concatenated
__device__ float g_t[2*Bz*S*D];
__device__ float g_cpart[(size_t)BH*64*S];  // per-(block,warp) partial col sums
__device__ float g_rinv[BH*S];              // 1/sum over t (per s)  -> ctx1
__device__ float g_cinv[BH*S];              // 1/sum over s (per t)  -> ctx2
__device__ int   g_mask_mode;               // 0=i32, 1=u8, 2=f32

// ---------------- helpers ----------------
__device__ __forceinline__ unsigned tf32c(float x) {
    unsigned u; asm("cvt.rna.tf32.f32 %0, %1;" : "=r"(u) : "f"(x)); return u;
}
__device__ __forceinline__ void mma8(float c[4], const unsigned a[4], const unsigned b[2]) {
    asm volatile(
        "mma.sync.aligned.m16n8k8.row.col.f32.tf32.tf32.f32 "
        "{%0,%1,%2,%3},{%4,%5,%6,%7},{%8,%9},{%0,%1,%2,%3};\n"
        : "+f"(c[0]), "+f"(c[1]), "+f"(c[2]), "+f"(c[3])
        : "r"(a[0]), "r"(a[1]), "r"(a[2]), "r"(a[3]), "r"(b[0]), "r"(b[1]));
}
__device__ __forceinline__ int kperm(int k) {
    return (k & ~7) + 2 * (k & 3) + ((k & 7) >> 2);
}

// ---------------- mask dtype sniffer ----------------
__global__ void detect_mask_kernel(const unsigned int* __restrict__ w) {
    __shared__ int s01, sf;
    if (threadIdx.x == 0) { s01 = 1; sf = 1; }
    __syncthreads();
    int a01 = 1, af = 1;
    for (int i = threadIdx.x; i < 4096; i += 256) {
        unsigned v = w[i];
        if (v != 0u && v != 1u) a01 = 0;
        if (v != 0u && v != 0x3F800000u) af = 0;
    }
    if (!a01) atomicAnd(&s01, 0);
    if (!af)  atomicAnd(&sf, 0);
    __syncthreads();
    if (threadIdx.x == 0) g_mask_mode = s01 ? 0 : (sf ? 2 : 1);
}

// ---------------- tf32 GEMM 128x128x32, register-staged double buffer ----------------
__global__ void __launch_bounds__(256) mm128_kernel(const float* __restrict__ A,
                                                    const float* __restrict__ B,
                                                    float* __restrict__ C) {
    __shared__ unsigned As[128 * 36];
    __shared__ unsigned Bs[32 * 132];
    const int m0 = blockIdx.y * 128, n0 = blockIdx.x * 128;
    const int tid = threadIdx.x, lane = tid & 31, w = tid >> 5;
    const int g = lane >> 2, tq = lane & 3;
    const int mw = (w & 1) * 64, nw = (w >> 1) * 32;
    const int kq = tid & 7, kc = kq * 4, bkp = (kq >> 1) * 8 + (kq & 1);
    const int arow = tid >> 3;
    const int bkr = tid >> 5, bnc = lane * 4;
    float4 ra[4], rb[4];
    float c[16][4] = {};

    #pragma unroll
    for (int it = 0; it < 4; it++)
        ra[it] = *(const float4*)(A + (size_t)(m0 + arow + it * 32) * 768 + kc);
    #pragma unroll
    for (int it = 0; it < 4; it++)
        rb[it] = *(const float4*)(B + (size_t)(bkr + it * 8) * 768 + n0 + bnc);
    #pragma unroll
    for (int it = 0; it < 4; it++) {
        unsigned* dst = &As[(arow + it * 32) * 36 + bkp];
        dst[0] = tf32c(ra[it].x); dst[2] = tf32c(ra[it].y);
        dst[4] = tf32c(ra[it].z); dst[6] = tf32c(ra[it].w);
        uint4 u; u.x = tf32c(rb[it].x); u.y = tf32c(rb[it].y);
        u.z = tf32c(rb[it].z); u.w = tf32c(rb[it].w);
        *(uint4*)&Bs[kperm(bkr + it * 8) * 132 + bnc] = u;
    }
    __syncthreads();

    for (int k0 = 0; k0 < 768; k0 += 32) {
        const bool more = (k0 + 32) < 768;
        if (more) {
            #pragma unroll
            for (int it = 0; it < 4; it++)
                ra[it] = *(const float4*)(A + (size_t)(m0 + arow + it * 32) * 768 + k0 + 32 + kc);
            #pragma unroll
            for (int it = 0; it < 4; it++)
                rb[it] = *(const float4*)(B + (size_t)(k0 + 32 + bkr + it * 8) * 768 + n0 + bnc);
        }
        #pragma unroll
        for (int ks = 0; ks < 4; ks++) {
            unsigned a[4][4], bf[4][2];
            #pragma unroll
            for (int i = 0; i < 4; i++) {
                int r = mw + 16 * i + g;
                uint2 x = *(const uint2*)&As[r * 36 + ks * 8 + 2 * tq];
                uint2 y = *(const uint2*)&As[(r + 8) * 36 + ks * 8 + 2 * tq];
                a[i][0] = x.x; a[i][1] = y.x; a[i][2] = x.y; a[i][3] = y.y;
            }
            #pragma unroll
            for (int j = 0; j < 4; j++) {
                int col = nw + 8 * j + g;
                bf[j][0] = Bs[(ks * 8 + 2 * tq) * 132 + col];
                bf[j][1] = Bs[(ks * 8 + 2 * tq + 1) * 132 + col];
            }
            #pragma unroll
            for (int i = 0; i < 4; i++)
                #pragma unroll
                for (int j = 0; j < 4; j++) mma8(c[i * 4 + j], a[i], bf[j]);
        }
        if (more) {
            __syncthreads();
            #pragma unroll
            for (int it = 0; it < 4; it++) {
                unsigned* dst = &As[(arow + it * 32) * 36 + bkp];
                dst[0] = tf32c(ra[it].x); dst[2] = tf32c(ra[it].y);
                dst[4] = tf32c(ra[it].z); dst[6] = tf32c(ra[it].w);
                uint4 u; u.x = tf32c(rb[it].x); u.y = tf32c(rb[it].y);
                u.z = tf32c(rb[it].z); u.w = tf32c(rb[it].w);
                *(uint4*)&Bs[kperm(bkr + it * 8) * 132 + bnc] = u;
            }
            __syncthreads();
        }
    }
    #pragma unroll
    for (int i = 0; i < 4; i++) {
        int r = m0 + mw + 16 * i + g;
        #pragma unroll
        for (int j = 0; j < 4; j++) {
            int col = n0 + nw + 8 * j + 2 * tq;
            *(float2*)(C + (size_t)r * 768 + col)       = make_float2(c[i*4+j][0], c[i*4+j][1]);
            *(float2*)(C + (size_t)(r + 8) * 768 + col) = make_float2(c[i*4+j][2], c[i*4+j][3]);
        }
    }
}

// ---------------- head transpose: X[b][s][h*64+d] -> XT[bh][d][s] ----------------
__global__ void tr_kernel(const float* __restrict__ X, float* __restrict__ XT) {
    __shared__ float tile[32][33];
    int bh = blockIdx.z, b = bh / H, h = bh % H;
    int s0 = blockIdx.x * 32, d0 = blockIdx.y * 32;
    int tx = threadIdx.x, ty = threadIdx.y;
    #pragma unroll
    for (int i = 0; i < 4; i++)
        tile[ty + 8 * i][tx] = X[(size_t)(b * S + s0 + ty + 8 * i) * D + h * DK + d0 + tx];
    __syncthreads();
    #pragma unroll
    for (int i = 0; i < 4; i++)
        XT[(size_t)(bh * DK + d0 + ty + 8 * i) * S + s0 + tx] = tile[tx][ty + 8 * i];
}

// ---------------- P[bh][t][s] = exp((K_t . Q_s)/8) or 0 if masked (fp16) ----------------
__global__ void __launch_bounds__(256) scoresT_kernel(const float* __restrict__ Kmat,
                                                      const float* __restrict__ QT,
                                                      const void* __restrict__ mask,
                                                      __half* __restrict__ P) {
    __shared__ unsigned As[128 * 36];
    __shared__ unsigned Bs[32 * 132];
    const int bh = blockIdx.z, b = bh / H, h = bh % H;
    const int s0 = blockIdx.x * 128, t0 = blockIdx.y * 128;
    const float* Ag = Kmat + (size_t)(b * S + t0) * D + h * DK;
    const float* Bg = QT + (size_t)bh * DK * S + s0;
    const int tid = threadIdx.x, lane = tid & 31, w = tid >> 5;
    const int g = lane >> 2, tq = lane & 3;
    const int mw = (w & 1) * 64, nw = (w >> 1) * 32;
    float c[16][4] = {};
    #pragma unroll
    for (int k0 = 0; k0 < 64; k0 += 32) {
        {
            int kq = tid & 7, kc = kq * 4, bkp = (kq >> 1) * 8 + (kq & 1);
            #pragma unroll
            for (int it = 0; it < 4; it++) {
                int m = (tid >> 3) + it * 32;
                float4 v = *(const float4*)(Ag + (size_t)m * D + k0 + kc);
                unsigned* dst = &As[m * 36 + bkp];
                dst[0] = tf32c(v.x); dst[2] = tf32c(v.y); dst[4] = tf32c(v.z); dst[6] = tf32c(v.w);
            }
        }
        {
            #pragma unroll
            for (int it = 0; it < 4; it++) {
                int kr = (tid >> 5) + it * 8;
                int nc = lane * 4;
                float4 v = *(const float4*)(Bg + (size_t)(k0 + kr) * S + nc);
                uint4 u; u.x = tf32c(v.x); u.y = tf32c(v.y); u.z = tf32c(v.z); u.w = tf32c(v.w);
                *(uint4*)&Bs[kperm(kr) * 132 + nc] = u;
            }
        }
        __syncthreads();
        #pragma unroll
        for (int ks = 0; ks < 4; ks++) {
            unsigned a[4][4], bf[4][2];
            #pragma unroll
            for (int i = 0; i < 4; i++) {
                int r = mw + 16 * i + g;
                uint2 x = *(const uint2*)&As[r * 36 + ks * 8 + 2 * tq];
                uint2 y = *(const uint2*)&As[(r + 8) * 36 + ks * 8 + 2 * tq];
                a[i][0] = x.x; a[i][1] = y.x; a[i][2] = x.y; a[i][3] = y.y;
            }
            #pragma unroll
            for (int j = 0; j < 4; j++) {
                int col = nw + 8 * j + g;
                bf[j][0] = Bs[(ks * 8 + 2 * tq) * 132 + col];
                bf[j][1] = Bs[(ks * 8 + 2 * tq + 1) * 132 + col];
            }
            #pragma unroll
            for (int i = 0; i < 4; i++)
                #pragma unroll
                for (int j = 0; j < 4; j++) mma8(c[i * 4 + j], a[i], bf[j]);
        }
        __syncthreads();
    }
    const int mode = g_mask_mode;
    const int* m32 = (const int*)mask;
    const unsigned char* m8 = (const unsigned char*)mask;
    const float* mf = (const float*)mask;
    #pragma unroll
    for (int i = 0; i < 4; i++) {
        int rA = t0 + mw + 16 * i + g;
        #pragma unroll
        for (int j = 0; j < 4; j++) {
            int cs = s0 + nw + 8 * j + 2 * tq;
            float* cc = c[i * 4 + j];
            size_t iA = ((size_t)bh * S + rA) * S + cs;
            size_t iB = iA + (size_t)8 * S;
            bool k0m, k1m, k2m, k3m;
            if (mode == 0) {
                int2 qa = *(const int2*)(m32 + iA); int2 qb = *(const int2*)(m32 + iB);
                k0m = qa.x != 0; k1m = qa.y != 0; k2m = qb.x != 0; k3m = qb.y != 0;
            } else if (mode == 1) {
                uchar2 qa = *(const uchar2*)(m8 + iA); uchar2 qb = *(const uchar2*)(m8 + iB);
                k0m = qa.x != 0; k1m = qa.y != 0; k2m = qb.x != 0; k3m = qb.y != 0;
            } else {
                float2 qa = *(const float2*)(mf + iA); float2 qb = *(const float2*)(mf + iB);
                k0m = qa.x != 0.0f; k1m = qa.y != 0.0f; k2m = qb.x != 0.0f; k3m = qb.y != 0.0f;
            }
            float p0 = k0m ? 0.0f : __expf(0.125f * cc[0]);
            float p1 = k1m ? 0.0f : __expf(0.125f * cc[1]);
            float p2 = k2m ? 0.0f : __expf(0.125f * cc[2]);
            float p3 = k3m ? 0.0f : __expf(0.125f * cc[3]);
            *(__half2*)(P + iA) = __floats2half2_rn(p0, p1);
            *(__half2*)(P + iB) = __floats2half2_rn(p2, p3);
        }
    }
}

// ---------------- fused dual sums over P (deterministic) ----------------
// Per block: 128 t-rows. Full sums over s (per t) -> cinv directly.
// Per-warp partial sums over t (per s) -> g_cpart, reduced by rinv_kernel.
__global__ void __launch_bounds__(256) sums_kernel(const __half* __restrict__ P,
                                                   float* __restrict__ cpart,
                                                   float* __restrict__ cinv) {
    int bh = blockIdx.y, blk = blockIdx.x;
    int w = threadIdx.x >> 5, lane = threadIdx.x & 31;
    int t0 = blk * 128 + w * 16;
    float colacc[8][4] = {};
    const __half* base = P + ((size_t)bh * S + t0) * S;
    for (int r = 0; r < 16; r++) {
        const __half* row = base + (size_t)r * S;
        float rsum = 0.f;
        #pragma unroll
        for (int k = 0; k < 8; k++) {
            uint2 u = *(const uint2*)(row + k * 128 + lane * 4);
            float2 fa = __half22float2(*(const __half2*)&u.x);
            float2 fb = __half22float2(*(const __half2*)&u.y);
            colacc[k][0] += fa.x; colacc[k][1] += fa.y;
            colacc[k][2] += fb.x; colacc[k][3] += fb.y;
            rsum += (fa.x + fa.y) + (fb.x + fb.y);
        }
        #pragma unroll
        for (int o = 16; o; o >>= 1) rsum += __shfl_xor_sync(0xffffffffu, rsum, o);
        if (lane == 0) cinv[bh * S + t0 + r] = 1.0f / rsum;
    }
    float* cp = cpart + ((size_t)bh * 64 + blk * 8 + w) * S;
    #pragma unroll
    for (int k = 0; k < 8; k++)
        *(float4*)(cp + k * 128 + lane * 4) =
            make_float4(colacc[k][0], colacc[k][1], colacc[k][2], colacc[k][3]);
}

__global__ void rinv_kernel(const float* __restrict__ cpart, float* __restrict__ rinv) {
    int bh = blockIdx.y;
    int s = blockIdx.x * 256 + threadIdx.x;
    const float* p = cpart + (size_t)bh * 64 * S + s;
    float sum = 0.f;
    #pragma unroll
    for (int j = 0; j < 64; j++) sum += p[(size_t)j * S];
    rinv[bh * S + s] = 1.0f / sum;
}

// ---------------- ctx1: C[b][s][h,d] = rinv[s] * sum_t KT[d][t] P[t][s] ----------------
__global__ void __launch_bounds__(256) ctx1_kernel(const float* __restrict__ KT,
                                                   const __half* __restrict__ P,
                                                   const float* __restrict__ rinv,
                                                   float* __restrict__ C) {
    __shared__ unsigned As[64 * 36];
    __shared__ unsigned Bs[32 * 268];
    __shared__ float ris[256];
    const int bh = blockIdx.y, b = bh / H, h = bh % H;
    const int s0 = blockIdx.x * 256;
    const float* Ag = KT + (size_t)bh * DK * S;
    const __half* Bg = P + (size_t)bh * S * S + s0;
    const int tid = threadIdx.x, lane = tid & 31, w = tid >> 5;
    const int g = lane >> 2, tq = lane & 3;
    const int nw = w * 32;
    const int kq = tid & 7, kc = kq * 4, bkp = (kq >> 1) * 8 + (kq & 1);
    const int arow = tid >> 3;
    const int bkr0 = tid >> 6, bnc = (tid & 63) * 4;
    ris[tid] = rinv[bh * S + s0 + tid];
    float4 ra[2]; uint2 rb[8];
    float c[16][4] = {};

    #pragma unroll
    for (int it = 0; it < 2; it++)
        ra[it] = *(const float4*)(Ag + (size_t)(arow + it * 32) * S + kc);
    #pragma unroll
    for (int it = 0; it < 8; it++)
        rb[it] = *(const uint2*)(Bg + (size_t)(bkr0 + it * 4) * S + bnc);
    #pragma unroll
    for (int it = 0; it < 2; it++) {
        unsigned* dst = &As[(arow + it * 32) * 36 + bkp];
        dst[0] = tf32c(ra[it].x); dst[2] = tf32c(ra[it].y);
        dst[4] = tf32c(ra[it].z); dst[6] = tf32c(ra[it].w);
    }
    #pragma unroll
    for (int it = 0; it < 8; it++) {
        float2 fa = __half22float2(*(const __half2*)&rb[it].x);
        float2 fb = __half22float2(*(const __half2*)&rb[it].y);
        uint4 u; u.x = tf32c(fa.x); u.y = tf32c(fa.y); u.z = tf32c(fb.x); u.w = tf32c(fb.y);
        *(uint4*)&Bs[kperm(bkr0 + it * 4) * 268 + bnc] = u;
    }
    __syncthreads();

    for (int k0 = 0; k0 < S; k0 += 32) {
        const bool more = (k0 + 32) < S;
        if (more) {
            #pragma unroll
            for (int it = 0; it < 2; it++)
                ra[it] = *(const float4*)(Ag + (size_t)(arow + it * 32) * S + k0 + 32 + kc);
            #pragma unroll
            for (int it = 0; it < 8; it++)
                rb[it] = *(const uint2*)(Bg + (size_t)(k0 + 32 + bkr0 + it * 4) * S + bnc);
        }
        #pragma unroll
        for (int ks = 0; ks < 4; ks++) {
            unsigned a[4][4], bf[4][2];
            #pragma unroll
            for (int i = 0; i < 4; i++) {
                int r = 16 * i + g;
                uint2 x = *(const uint2*)&As[r * 36 + ks * 8 + 2 * tq];
                uint2 y = *(const uint2*)&As[(r + 8) * 36 + ks * 8 + 2 * tq];
                a[i][0] = x.x; a[i][1] = y.x; a[i][2] = x.y; a[i][3] = y.y;
            }
            #pragma unroll
            for (int j = 0; j < 4; j++) {
                int col = nw + 8 * j + g;
                bf[j][0] = Bs[(ks * 8 + 2 * tq) * 268 + col];
                bf[j][1] = Bs[(ks * 8 + 2 * tq + 1) * 268 + col];
            }
            #pragma unroll
            for (int i = 0; i < 4; i++)
                #pragma unroll
                for (int j = 0; j < 4; j++) mma8(c[i * 4 + j], a[i], bf[j]);
        }
        if (more) {
            __syncthreads();
            #pragma unroll
            for (int it = 0; it < 2; it++) {
                unsigned* dst = &As[(arow + it * 32) * 36 + bkp];
                dst[0] = tf32c(ra[it].x); dst[2] = tf32c(ra[it].y);
                dst[4] = tf32c(ra[it].z); dst[6] = tf32c(ra[it].w);
            }
            #pragma unroll
            for (int it = 0; it < 8; it++) {
                float2 fa = __half22float2(*(const __half2*)&rb[it].x);
                float2 fb = __half22float2(*(const __half2*)&rb[it].y);
                uint4 u; u.x = tf32c(fa.x); u.y = tf32c(fa.y); u.z = tf32c(fb.x); u.w = tf32c(fb.y);
                *(uint4*)&Bs[kperm(bkr0 + it * 4) * 268 + bnc] = u;
            }
            __syncthreads();
        }
    }
    #pragma unroll
    for (int i = 0; i < 4; i++) {
        int d = 16 * i + g;
        #pragma unroll
        for (int j = 0; j < 4; j++) {
            int sl = nw + 8 * j + 2 * tq;
            int s = s0 + sl;
            float* cc = c[i * 4 + j];
            float r0 = ris[sl], r1 = ris[sl + 1];
            size_t a0 = (size_t)(b * S + s) * D + h * DK + d;
            C[a0]         = cc[0] * r0;
            C[a0 + D]     = cc[1] * r1;
            C[a0 + 8]     = cc[2] * r0;
            C[a0 + D + 8] = cc[3] * r1;
        }
    }
}

// ---------------- ctx2: C[b][t][h,d] = cinv[t] * sum_s P[t][s] Q[s][d] ----------------
__global__ void __launch_bounds__(256) ctx2_kernel(const __half* __restrict__ P,
                                                   const float* __restrict__ Q,
                                                   const float* __restrict__ cinv,
                                                   float* __restrict__ C) {
    __shared__ unsigned As[256 * 36];
    __shared__ unsigned Bs[32 * 68];
    __shared__ float cis[256];
    const int bh = blockIdx.y, b = bh / H, h = bh % H;
    const int t0 = blockIdx.x * 256;
    const __half* Ag = P + ((size_t)bh * S + t0) * S;
    const float* Bg = Q + (size_t)b * S * D + h * DK;
    const int tid = threadIdx.x, lane = tid & 31, w = tid >> 5;
    const int g = lane >> 2, tq = lane & 3;
    const int mw = (w >> 1) * 64, nw = (w & 1) * 32;
    const int kq = tid & 7, kc = kq * 4, bkp = (kq >> 1) * 8 + (kq & 1);
    const int arow = tid >> 3;
    const int bkr0 = tid >> 4, bnc = (tid & 15) * 4;
    cis[tid] = cinv[bh * S + t0 + tid];
    uint2 ra[8]; float4 rb[2];
    float c[16][4] = {};

    #pragma unroll
    for (int it = 0; it < 8; it++)
        ra[it] = *(const uint2*)(Ag + (size_t)(arow + it * 32) * S + kc);
    #pragma unroll
    for (int it = 0; it < 2; it++)
        rb[it] = *(const float4*)(Bg + (size_t)(bkr0 + it * 16) * D + bnc);
    #pragma unroll
    for (int it = 0; it < 8; it++) {
        float2 fa = __half22float2(*(const __half2*)&ra[it].x);
        float2 fb = __half22float2(*(const __half2*)&ra[it].y);
        unsigned* dst = &As[(arow + it * 32) * 36 + bkp];
        dst[0] = tf32c(fa.x); dst[2] = tf32c(fa.y); dst[4] = tf32c(fb.x); dst[6] = tf32c(fb.y);
    }
    #pragma unroll
    for (int it = 0; it < 2; it++) {
        uint4 u; u.x = tf32c(rb[it].x); u.y = tf32c(rb[it].y);
        u.z = tf32c(rb[it].z); u.w = tf32c(rb[it].w);
        *(uint4*)&Bs[kperm(bkr0 + it * 16) * 68 + bnc] = u;
    }
    __syncthreads();

    for (int k0 = 0; k0 < S; k0 += 32) {
        const bool more = (k0 + 32) < S;
        if (more) {
            #pragma unroll
            for (int it = 0; it < 8; it++)
                ra[it] = *(const uint2*)(Ag + (size_t)(arow + it * 32) * S + k0 + 32 + kc);
            #pragma unroll
            for (int it = 0; it < 2; it++)
                rb[it] = *(const float4*)(Bg + (size_t)(k0 + 32 + bkr0 + it * 16) * D + bnc);
        }
        #pragma unroll
        for (int ks = 0; ks < 4; ks++) {
            unsigned a[4][4], bf[2][2];
            #pragma unroll
            for (int i = 0; i < 4; i++) {
                int r = mw + 16 * i + g;
                uint2 x = *(const uint2*)&As[r * 36 + ks * 8 + 2 * tq];
                uint2 y = *(const uint2*)&As[(r + 8) * 36 + ks * 8 + 2 * tq];
                a[i][0] = x.x; a[i][1] = y.x; a[i][2] = x.y; a[i][3] = y.y;
            }
            #pragma unroll
            for (int j = 0; j < 4; j++) {
                int col = nw + 8 * j + g;
                bf[j & 1][0] = Bs[(ks * 8 + 2 * tq) * 68 + col];
                bf[j & 1][1] = Bs[(ks * 8 + 2 * tq + 1) * 68 + col];
                #pragma unroll
                for (int i = 0; i < 4; i++) mma8(c[i * 4 + j], a[i], bf[j & 1]);
            }
        }
        if (more) {
            __syncthreads();
            #pragma unroll
            for (int it = 0; it < 8; it++) {
                float2 fa = __half22float2(*(const __half2*)&ra[it].x);
                float2 fb = __half22float2(*(const __half2*)&ra[it].y);
                unsigned* dst = &As[(arow + it * 32) * 36 + bkp];
                dst[0] = tf32c(fa.x); dst[2] = tf32c(fa.y); dst[4] = tf32c(fb.x); dst[6] = tf32c(fb.y);
            }
            #pragma unroll
            for (int it = 0; it < 2; it++) {
                uint4 u; u.x = tf32c(rb[it].x); u.y = tf32c(rb[it].y);
                u.z = tf32c(rb[it].z); u.w = tf32c(rb[it].w);
                *(uint4*)&Bs[kperm(bkr0 + it * 16) * 68 + bnc] = u;
            }
            __syncthreads();
        }
    }
    #pragma unroll
    for (int i = 0; i < 4; i++) {
        int tl = mw + 16 * i + g;
        int t = t0 + tl;
        float ci0 = cis[tl], ci8 = cis[tl + 8];
        #pragma unroll
        for (int j = 0; j < 4; j++) {
            int dcol = nw + 8 * j + 2 * tq;
            float* cc = c[i * 4 + j];
            size_t a0 = (size_t)(b * S + t) * D + h * DK + dcol;
            *(float2*)(C + a0)                 = make_float2(cc[0] * ci0, cc[1] * ci0);
            *(float2*)(C + a0 + (size_t)8 * D) = make_float2(cc[2] * ci8, cc[3] * ci8);
        }
    }
}

// ---------------- batched LayerNorm over last dim (768); rows 0..4095 use g1/b1 ----------------
__global__ void ln_kernel(const float* __restrict__ x,
                          const float* __restrict__ g1, const float* __restrict__ b1,
                          const float* __restrict__ g2, const float* __restrict__ b2,
                          float* __restrict__ out) {
    int row = blockIdx.x, tid = threadIdx.x;
    const float* gg = (row < Bz * S) ? g1 : g2;
    const float* bb = (row < Bz * S) ? b1 : b2;
    const float* xr = x + (size_t)row * D;
    float v0 = xr[tid], v1 = xr[tid + 256], v2 = xr[tid + 512];
    float s = v0 + v1 + v2;
    __shared__ float red[8];
    #pragma unroll
    for (int o = 16; o; o >>= 1) s += __shfl_xor_sync(0xffffffffu, s, o);
    if ((tid & 31) == 0) red[tid >> 5] = s;
    __syncthreads();
    float tot = 0.f;
    #pragma unroll
    for (int i = 0; i < 8; i++) tot += red[i];
    float mu = tot * (1.0f / 768.0f);
    float d0 = v0 - mu, d1 = v1 - mu, d2 = v2 - mu;
    float q = d0 * d0 + d1 * d1 + d2 * d2;
    #pragma unroll
    for (int o = 16; o; o >>= 1) q += __shfl_xor_sync(0xffffffffu, q, o);
    __syncthreads();
    if ((tid & 31) == 0) red[tid >> 5] = q;
    __syncthreads();
    float var = 0.f;
    #pragma unroll
    for (int i = 0; i < 8; i++) var += red[i];
    var *= (1.0f / 768.0f);
    float rs = rsqrtf(var + 1e-5f);
    float* orow = out + (size_t)row * D;
    orow[tid]       = d0 * rs * gg[tid]       + bb[tid];
    orow[tid + 256] = d1 * rs * gg[tid + 256] + bb[tid + 256];
    orow[tid + 512] = d2 * rs * gg[tid + 512] + bb[tid + 512];
}

// ---------------- launch ----------------
extern "C" void kernel_launch(void* const* d_in, const int* in_sizes, int n_in,
                              void* d_out, int out_size) {
    const float* pro1 = (const float*)d_in[0];
    const float* pro2 = (const float*)d_in[1];
    const void*  mask = d_in[2];
    const float* W_Q  = (const float*)d_in[3];
    const float* W_K  = (const float*)d_in[4];
    const float* fc1  = (const float*)d_in[5];
    const float* g1   = (const float*)d_in[6];
    const float* b1   = (const float*)d_in[7];
    const float* g2   = (const float*)d_in[8];
    const float* b2   = (const float*)d_in[9];
    float* out = (float*)d_out;

    float *Qp, *Kp, *QTp, *KTp, *CX, *Tp, *CP, *RI, *CI;
    __half* Pp;
    cudaGetSymbolAddress((void**)&Qp, g_Q);
    cudaGetSymbolAddress((void**)&Kp, g_K);
    cudaGetSymbolAddress((void**)&QTp, g_QT);
    cudaGetSymbolAddress((void**)&KTp, g_KT);
    cudaGetSymbolAddress((void**)&Pp, g_P);
    cudaGetSymbolAddress((void**)&CX, g_ctx);
    cudaGetSymbolAddress((void**)&Tp, g_t);
    cudaGetSymbolAddress((void**)&CP, g_cpart);
    cudaGetSymbolAddress((void**)&RI, g_rinv);
    cudaGetSymbolAddress((void**)&CI, g_cinv);

    detect_mask_kernel<<<1, 256>>>((const unsigned int*)mask);

    dim3 gProj(6, 32);
    mm128_kernel<<<gProj, 256>>>(pro1, W_Q, Qp);
    mm128_kernel<<<gProj, 256>>>(pro2, W_K, Kp);

    tr_kernel<<<dim3(32, 2, BH), dim3(32, 8)>>>(Qp, QTp);
    tr_kernel<<<dim3(32, 2, BH), dim3(32, 8)>>>(Kp, KTp);

    scoresT_kernel<<<dim3(8, 8, BH), 256>>>(Kp, QTp, mask, Pp);

    sums_kernel<<<dim3(8, BH), 256>>>(Pp, CP, CI);
    rinv_kernel<<<dim3(4, BH), 256>>>(CP, RI);

    ctx1_kernel<<<dim3(4, BH), 256>>>(KTp, Pp, RI, CX);
    ctx2_kernel<<<dim3(4, BH), 256>>>(Pp, Qp, CI, CX + (size_t)Bz * S * D);

    mm128_kernel<<<dim3(6, 64), 256>>>(CX, fc1, Tp);

    ln_kernel<<<2 * Bz * S, 256>>>(Tp, g1, b1, g2, b2, out);
}

// round 4
// speedup vs baseline: 1.0067x; 1.0067x over previous
#include <cuda_runtime.h>
#include <cuda_fp16.h>
#include <cstdint>

#define Bz 4
#define S 1024
#define D 768
#define H 12
#define DK 64
#define BH (Bz*H)

// ---------------- scratch (device globals) ----------------
__device__ float g_Q[Bz*S*D];
__device__ float g_K[Bz*S*D];
__device__ float g_QT[BH*DK*S];
__device__ float g_KT[BH*DK*S];
__device__ __half g_P[(size_t)BH*S*S];      // P = exp(score) (0 where masked), layout [bh][t][s]
__device__ float g_ctx[2*Bz*S*D];           // ctx1 | ctx2 concatenated
__device__ float g_t[2*Bz*S*D];
__device__ float g_cpart[(size_t)BH*64*S];  // per-(block,warp) partial col sums
__device__ float g_rinv[BH*S];              // 1/sum over t (per s)  -> ctx1
__device__ float g_cinv[BH*S];              // 1/sum over s (per t)  -> ctx2
__device__ int   g_mask_mode;               // 0=i32, 1=u8, 2=f32

// ---------------- helpers ----------------
__device__ __forceinline__ unsigned tf32c(float x) {
    unsigned u; asm("cvt.rna.tf32.f32 %0, %1;" : "=r"(u) : "f"(x)); return u;
}
__device__ __forceinline__ void mma8(float c[4], const unsigned a[4], const unsigned b[2]) {
    asm volatile(
        "mma.sync.aligned.m16n8k8.row.col.f32.tf32.tf32.f32 "
        "{%0,%1,%2,%3},{%4,%5,%6,%7},{%8,%9},{%0,%1,%2,%3};\n"
        : "+f"(c[0]), "+f"(c[1]), "+f"(c[2]), "+f"(c[3])
        : "r"(a[0]), "r"(a[1]), "r"(a[2]), "r"(a[3]), "r"(b[0]), "r"(b[1]));
}
__device__ __forceinline__ int kperm(int k) {
    return (k & ~7) + 2 * (k & 3) + ((k & 7) >> 2);
}

// ---------------- mask dtype sniffer ----------------
__global__ void detect_mask_kernel(const unsigned int* __restrict__ w) {
    __shared__ int s01, sf;
    if (threadIdx.x == 0) { s01 = 1; sf = 1; }
    __syncthreads();
    int a01 = 1, af = 1;
    for (int i = threadIdx.x; i < 4096; i += 256) {
        unsigned v = w[i];
        if (v != 0u && v != 1u) a01 = 0;
        if (v != 0u && v != 0x3F800000u) af = 0;
    }
    if (!a01) atomicAnd(&s01, 0);
    if (!af)  atomicAnd(&sf, 0);
    __syncthreads();
    if (threadIdx.x == 0) g_mask_mode = s01 ? 0 : (sf ? 2 : 1);
}

// ---------------- tf32 GEMM 128x128x32 (single-buffered, R2 structure) ----------------
__global__ void __launch_bounds__(256) mm128_kernel(const float* __restrict__ A,
                                                    const float* __restrict__ B,
                                                    float* __restrict__ C) {
    __shared__ unsigned As[128 * 36];
    __shared__ unsigned Bs[32 * 132];
    const int m0 = blockIdx.y * 128, n0 = blockIdx.x * 128;
    const int tid = threadIdx.x, lane = tid & 31, w = tid >> 5;
    const int g = lane >> 2, tq = lane & 3;
    const int mw = (w & 1) * 64, nw = (w >> 1) * 32;
    float c[16][4] = {};
    for (int k0 = 0; k0 < 768; k0 += 32) {
        {   // A: 128x32
            int kq = tid & 7, kc = kq * 4, bkp = (kq >> 1) * 8 + (kq & 1);
            #pragma unroll
            for (int it = 0; it < 4; it++) {
                int m = (tid >> 3) + it * 32;
                float4 v = *(const float4*)(A + (size_t)(m0 + m) * 768 + k0 + kc);
                unsigned* dst = &As[m * 36 + bkp];
                dst[0] = tf32c(v.x); dst[2] = tf32c(v.y); dst[4] = tf32c(v.z); dst[6] = tf32c(v.w);
            }
        }
        {   // B: 32x128
            #pragma unroll
            for (int it = 0; it < 4; it++) {
                int kr = (tid >> 5) + it * 8;
                int nc = lane * 4;
                float4 v = *(const float4*)(B + (size_t)(k0 + kr) * 768 + n0 + nc);
                uint4 u; u.x = tf32c(v.x); u.y = tf32c(v.y); u.z = tf32c(v.z); u.w = tf32c(v.w);
                *(uint4*)&Bs[kperm(kr) * 132 + nc] = u;
            }
        }
        __syncthreads();
        #pragma unroll
        for (int ks = 0; ks < 4; ks++) {
            unsigned a[4][4], bf[4][2];
            #pragma unroll
            for (int i = 0; i < 4; i++) {
                int r = mw + 16 * i + g;
                uint2 x = *(const uint2*)&As[r * 36 + ks * 8 + 2 * tq];
                uint2 y = *(const uint2*)&As[(r + 8) * 36 + ks * 8 + 2 * tq];
                a[i][0] = x.x; a[i][1] = y.x; a[i][2] = x.y; a[i][3] = y.y;
            }
            #pragma unroll
            for (int j = 0; j < 4; j++) {
                int col = nw + 8 * j + g;
                bf[j][0] = Bs[(ks * 8 + 2 * tq) * 132 + col];
                bf[j][1] = Bs[(ks * 8 + 2 * tq + 1) * 132 + col];
            }
            #pragma unroll
            for (int i = 0; i < 4; i++)
                #pragma unroll
                for (int j = 0; j < 4; j++) mma8(c[i * 4 + j], a[i], bf[j]);
        }
        __syncthreads();
    }
    #pragma unroll
    for (int i = 0; i < 4; i++) {
        int r = m0 + mw + 16 * i + g;
        #pragma unroll
        for (int j = 0; j < 4; j++) {
            int col = n0 + nw + 8 * j + 2 * tq;
            *(float2*)(C + (size_t)r * 768 + col)       = make_float2(c[i*4+j][0], c[i*4+j][1]);
            *(float2*)(C + (size_t)(r + 8) * 768 + col) = make_float2(c[i*4+j][2], c[i*4+j][3]);
        }
    }
}

// ---------------- head transpose: X[b][s][h*64+d] -> XT[bh][d][s] ----------------
__global__ void tr_kernel(const float* __restrict__ X, float* __restrict__ XT) {
    __shared__ float tile[32][33];
    int bh = blockIdx.z, b = bh / H, h = bh % H;
    int s0 = blockIdx.x * 32, d0 = blockIdx.y * 32;
    int tx = threadIdx.x, ty = threadIdx.y;
    #pragma unroll
    for (int i = 0; i < 4; i++)
        tile[ty + 8 * i][tx] = X[(size_t)(b * S + s0 + ty + 8 * i) * D + h * DK + d0 + tx];
    __syncthreads();
    #pragma unroll
    for (int i = 0; i < 4; i++)
        XT[(size_t)(bh * DK + d0 + ty + 8 * i) * S + s0 + tx] = tile[tx][ty + 8 * i];
}

// ---------------- P[bh][t][s] = exp((K_t . Q_s)/8) or 0 if masked (fp16) ----------------
__global__ void __launch_bounds__(256) scoresT_kernel(const float* __restrict__ Kmat,
                                                      const float* __restrict__ QT,
                                                      const void* __restrict__ mask,
                                                      __half* __restrict__ P) {
    __shared__ unsigned As[128 * 36];
    __shared__ unsigned Bs[32 * 132];
    const int bh = blockIdx.z, b = bh / H, h = bh % H;
    const int s0 = blockIdx.x * 128, t0 = blockIdx.y * 128;
    const float* Ag = Kmat + (size_t)(b * S + t0) * D + h * DK;
    const float* Bg = QT + (size_t)bh * DK * S + s0;
    const int tid = threadIdx.x, lane = tid & 31, w = tid >> 5;
    const int g = lane >> 2, tq = lane & 3;
    const int mw = (w & 1) * 64, nw = (w >> 1) * 32;
    float c[16][4] = {};
    #pragma unroll
    for (int k0 = 0; k0 < 64; k0 += 32) {
        {
            int kq = tid & 7, kc = kq * 4, bkp = (kq >> 1) * 8 + (kq & 1);
            #pragma unroll
            for (int it = 0; it < 4; it++) {
                int m = (tid >> 3) + it * 32;
                float4 v = *(const float4*)(Ag + (size_t)m * D + k0 + kc);
                unsigned* dst = &As[m * 36 + bkp];
                dst[0] = tf32c(v.x); dst[2] = tf32c(v.y); dst[4] = tf32c(v.z); dst[6] = tf32c(v.w);
            }
        }
        {
            #pragma unroll
            for (int it = 0; it < 4; it++) {
                int kr = (tid >> 5) + it * 8;
                int nc = lane * 4;
                float4 v = *(const float4*)(Bg + (size_t)(k0 + kr) * S + nc);
                uint4 u; u.x = tf32c(v.x); u.y = tf32c(v.y); u.z = tf32c(v.z); u.w = tf32c(v.w);
                *(uint4*)&Bs[kperm(kr) * 132 + nc] = u;
            }
        }
        __syncthreads();
        #pragma unroll
        for (int ks = 0; ks < 4; ks++) {
            unsigned a[4][4], bf[4][2];
            #pragma unroll
            for (int i = 0; i < 4; i++) {
                int r = mw + 16 * i + g;
                uint2 x = *(const uint2*)&As[r * 36 + ks * 8 + 2 * tq];
                uint2 y = *(const uint2*)&As[(r + 8) * 36 + ks * 8 + 2 * tq];
                a[i][0] = x.x; a[i][1] = y.x; a[i][2] = x.y; a[i][3] = y.y;
            }
            #pragma unroll
            for (int j = 0; j < 4; j++) {
                int col = nw + 8 * j + g;
                bf[j][0] = Bs[(ks * 8 + 2 * tq) * 132 + col];
                bf[j][1] = Bs[(ks * 8 + 2 * tq + 1) * 132 + col];
            }
            #pragma unroll
            for (int i = 0; i < 4; i++)
                #pragma unroll
                for (int j = 0; j < 4; j++) mma8(c[i * 4 + j], a[i], bf[j]);
        }
        __syncthreads();
    }
    const int mode = g_mask_mode;
    const int* m32 = (const int*)mask;
    const unsigned char* m8 = (const unsigned char*)mask;
    const float* mf = (const float*)mask;
    #pragma unroll
    for (int i = 0; i < 4; i++) {
        int rA = t0 + mw + 16 * i + g;
        #pragma unroll
        for (int j = 0; j < 4; j++) {
            int cs = s0 + nw + 8 * j + 2 * tq;
            float* cc = c[i * 4 + j];
            size_t iA = ((size_t)bh * S + rA) * S + cs;
            size_t iB = iA + (size_t)8 * S;
            bool k0m, k1m, k2m, k3m;
            if (mode == 0) {
                int2 qa = *(const int2*)(m32 + iA); int2 qb = *(const int2*)(m32 + iB);
                k0m = qa.x != 0; k1m = qa.y != 0; k2m = qb.x != 0; k3m = qb.y != 0;
            } else if (mode == 1) {
                uchar2 qa = *(const uchar2*)(m8 + iA); uchar2 qb = *(const uchar2*)(m8 + iB);
                k0m = qa.x != 0; k1m = qa.y != 0; k2m = qb.x != 0; k3m = qb.y != 0;
            } else {
                float2 qa = *(const float2*)(mf + iA); float2 qb = *(const float2*)(mf + iB);
                k0m = qa.x != 0.0f; k1m = qa.y != 0.0f; k2m = qb.x != 0.0f; k3m = qb.y != 0.0f;
            }
            float p0 = k0m ? 0.0f : __expf(0.125f * cc[0]);
            float p1 = k1m ? 0.0f : __expf(0.125f * cc[1]);
            float p2 = k2m ? 0.0f : __expf(0.125f * cc[2]);
            float p3 = k3m ? 0.0f : __expf(0.125f * cc[3]);
            *(__half2*)(P + iA) = __floats2half2_rn(p0, p1);
            *(__half2*)(P + iB) = __floats2half2_rn(p2, p3);
        }
    }
}

// ---------------- fused dual sums over P (deterministic) ----------------
__global__ void __launch_bounds__(256) sums_kernel(const __half* __restrict__ P,
                                                   float* __restrict__ cpart,
                                                   float* __restrict__ cinv) {
    int bh = blockIdx.y, blk = blockIdx.x;
    int w = threadIdx.x >> 5, lane = threadIdx.x & 31;
    int t0 = blk * 128 + w * 16;
    float colacc[8][4] = {};
    const __half* base = P + ((size_t)bh * S + t0) * S;
    for (int r = 0; r < 16; r++) {
        const __half* row = base + (size_t)r * S;
        float rsum = 0.f;
        #pragma unroll
        for (int k = 0; k < 8; k++) {
            uint2 u = *(const uint2*)(row + k * 128 + lane * 4);
            float2 fa = __half22float2(*(const __half2*)&u.x);
            float2 fb = __half22float2(*(const __half2*)&u.y);
            colacc[k][0] += fa.x; colacc[k][1] += fa.y;
            colacc[k][2] += fb.x; colacc[k][3] += fb.y;
            rsum += (fa.x + fa.y) + (fb.x + fb.y);
        }
        #pragma unroll
        for (int o = 16; o; o >>= 1) rsum += __shfl_xor_sync(0xffffffffu, rsum, o);
        if (lane == 0) cinv[bh * S + t0 + r] = 1.0f / rsum;
    }
    float* cp = cpart + ((size_t)bh * 64 + blk * 8 + w) * S;
    #pragma unroll
    for (int k = 0; k < 8; k++)
        *(float4*)(cp + k * 128 + lane * 4) =
            make_float4(colacc[k][0], colacc[k][1], colacc[k][2], colacc[k][3]);
}

__global__ void rinv_kernel(const float* __restrict__ cpart, float* __restrict__ rinv) {
    int bh = blockIdx.y;
    int s = blockIdx.x * 256 + threadIdx.x;
    const float* p = cpart + (size_t)bh * 64 * S + s;
    float sum = 0.f;
    #pragma unroll
    for (int j = 0; j < 64; j++) sum += p[(size_t)j * S];
    rinv[bh * S + s] = 1.0f / sum;
}

// ---------------- ctx1: C[b][s][h,d] = rinv[s] * sum_t KT[d][t] P[t][s] ----------------
// m=d(64), n=s(256), k=t. Single-buffered.
__global__ void __launch_bounds__(256) ctx1_kernel(const float* __restrict__ KT,
                                                   const __half* __restrict__ P,
                                                   const float* __restrict__ rinv,
                                                   float* __restrict__ C) {
    __shared__ unsigned As[64 * 36];
    __shared__ unsigned Bs[32 * 268];
    __shared__ float ris[256];
    const int bh = blockIdx.y, b = bh / H, h = bh % H;
    const int s0 = blockIdx.x * 256;
    const float* Ag = KT + (size_t)bh * DK * S;
    const __half* Bg = P + (size_t)bh * S * S + s0;
    const int tid = threadIdx.x, lane = tid & 31, w = tid >> 5;
    const int g = lane >> 2, tq = lane & 3;
    const int nw = w * 32;
    ris[tid] = rinv[bh * S + s0 + tid];
    __syncthreads();
    float c[16][4] = {};
    for (int k0 = 0; k0 < S; k0 += 32) {
        {   // A: 64 x 32 from KT rows
            int kq = tid & 7, kc = kq * 4, bkp = (kq >> 1) * 8 + (kq & 1);
            #pragma unroll
            for (int it = 0; it < 2; it++) {
                int m = (tid >> 3) + it * 32;
                float4 v = *(const float4*)(Ag + (size_t)m * S + k0 + kc);
                unsigned* dst = &As[m * 36 + bkp];
                dst[0] = tf32c(v.x); dst[2] = tf32c(v.y); dst[4] = tf32c(v.z); dst[6] = tf32c(v.w);
            }
        }
        {   // B: 32 x 256 fp16 P rows
            #pragma unroll
            for (int it = 0; it < 8; it++) {
                int kr = (tid >> 6) + it * 4;
                int nc = (tid & 63) * 4;
                uint2 u2 = *(const uint2*)(Bg + (size_t)(k0 + kr) * S + nc);
                float2 fa = __half22float2(*(const __half2*)&u2.x);
                float2 fb = __half22float2(*(const __half2*)&u2.y);
                uint4 u; u.x = tf32c(fa.x); u.y = tf32c(fa.y); u.z = tf32c(fb.x); u.w = tf32c(fb.y);
                *(uint4*)&Bs[kperm(kr) * 268 + nc] = u;
            }
        }
        __syncthreads();
        #pragma unroll
        for (int ks = 0; ks < 4; ks++) {
            unsigned a[4][4], bf[4][2];
            #pragma unroll
            for (int i = 0; i < 4; i++) {
                int r = 16 * i + g;
                uint2 x = *(const uint2*)&As[r * 36 + ks * 8 + 2 * tq];
                uint2 y = *(const uint2*)&As[(r + 8) * 36 + ks * 8 + 2 * tq];
                a[i][0] = x.x; a[i][1] = y.x; a[i][2] = x.y; a[i][3] = y.y;
            }
            #pragma unroll
            for (int j = 0; j < 4; j++) {
                int col = nw + 8 * j + g;
                bf[j][0] = Bs[(ks * 8 + 2 * tq) * 268 + col];
                bf[j][1] = Bs[(ks * 8 + 2 * tq + 1) * 268 + col];
            }
            #pragma unroll
            for (int i = 0; i < 4; i++)
                #pragma unroll
                for (int j = 0; j < 4; j++) mma8(c[i * 4 + j], a[i], bf[j]);
        }
        __syncthreads();
    }
    #pragma unroll
    for (int i = 0; i < 4; i++) {
        int d = 16 * i + g;
        #pragma unroll
        for (int j = 0; j < 4; j++) {
            int sl = nw + 8 * j + 2 * tq;
            int s = s0 + sl;
            float* cc = c[i * 4 + j];
            float r0 = ris[sl], r1 = ris[sl + 1];
            size_t a0 = (size_t)(b * S + s) * D + h * DK + d;
            C[a0]         = cc[0] * r0;
            C[a0 + D]     = cc[1] * r1;
            C[a0 + 8]     = cc[2] * r0;
            C[a0 + D + 8] = cc[3] * r1;
        }
    }
}

// ---------------- ctx2: C[b][t][h,d] = cinv[t] * sum_s P[t][s] Q[s][d] ----------------
// m=t(256), n=d(64), k=s. Single-buffered.
__global__ void __launch_bounds__(256) ctx2_kernel(const __half* __restrict__ P,
                                                   const float* __restrict__ Q,
                                                   const float* __restrict__ cinv,
                                                   float* __restrict__ C) {
    __shared__ unsigned As[256 * 36];
    __shared__ unsigned Bs[32 * 68];
    __shared__ float cis[256];
    const int bh = blockIdx.y, b = bh / H, h = bh % H;
    const int t0 = blockIdx.x * 256;
    const __half* Ag = P + ((size_t)bh * S + t0) * S;
    const float* Bg = Q + (size_t)b * S * D + h * DK;
    const int tid = threadIdx.x, lane = tid & 31, w = tid >> 5;
    const int g = lane >> 2, tq = lane & 3;
    const int mw = (w >> 1) * 64, nw = (w & 1) * 32;
    cis[tid] = cinv[bh * S + t0 + tid];
    __syncthreads();
    float c[16][4] = {};
    for (int k0 = 0; k0 < S; k0 += 32) {
        {   // A: 256 x 32 fp16 P
            int kq = tid & 7, kc = kq * 4, bkp = (kq >> 1) * 8 + (kq & 1);
            #pragma unroll
            for (int it = 0; it < 8; it++) {
                int m = (tid >> 3) + it * 32;
                uint2 u2 = *(const uint2*)(Ag + (size_t)m * S + k0 + kc);
                float2 fa = __half22float2(*(const __half2*)&u2.x);
                float2 fb = __half22float2(*(const __half2*)&u2.y);
                unsigned* dst = &As[m * 36 + bkp];
                dst[0] = tf32c(fa.x); dst[2] = tf32c(fa.y); dst[4] = tf32c(fb.x); dst[6] = tf32c(fb.y);
            }
        }
        {   // B: 32 x 64 from Q rows
            #pragma unroll
            for (int it = 0; it < 2; it++) {
                int kr = (tid >> 4) + it * 16;
                int nc = (tid & 15) * 4;
                float4 v = *(const float4*)(Bg + (size_t)(k0 + kr) * D + nc);
                uint4 u; u.x = tf32c(v.x); u.y = tf32c(v.y); u.z = tf32c(v.z); u.w = tf32c(v.w);
                *(uint4*)&Bs[kperm(kr) * 68 + nc] = u;
            }
        }
        __syncthreads();
        #pragma unroll
        for (int ks = 0; ks < 4; ks++) {
            unsigned a[4][4], bf[2][2];
            #pragma unroll
            for (int i = 0; i < 4; i++) {
                int r = mw + 16 * i + g;
                uint2 x = *(const uint2*)&As[r * 36 + ks * 8 + 2 * tq];
                uint2 y = *(const uint2*)&As[(r + 8) * 36 + ks * 8 + 2 * tq];
                a[i][0] = x.x; a[i][1] = y.x; a[i][2] = x.y; a[i][3] = y.y;
            }
            #pragma unroll
            for (int j = 0; j < 4; j++) {
                int col = nw + 8 * j + g;
                bf[j & 1][0] = Bs[(ks * 8 + 2 * tq) * 68 + col];
                bf[j & 1][1] = Bs[(ks * 8 + 2 * tq + 1) * 68 + col];
                #pragma unroll
                for (int i = 0; i < 4; i++) mma8(c[i * 4 + j], a[i], bf[j & 1]);
            }
        }
        __syncthreads();
    }
    #pragma unroll
    for (int i = 0; i < 4; i++) {
        int tl = mw + 16 * i + g;
        int t = t0 + tl;
        float ci0 = cis[tl], ci8 = cis[tl + 8];
        #pragma unroll
        for (int j = 0; j < 4; j++) {
            int dcol = nw + 8 * j + 2 * tq;
            float* cc = c[i * 4 + j];
            size_t a0 = (size_t)(b * S + t) * D + h * DK + dcol;
            *(float2*)(C + a0)                 = make_float2(cc[0] * ci0, cc[1] * ci0);
            *(float2*)(C + a0 + (size_t)8 * D) = make_float2(cc[2] * ci8, cc[3] * ci8);
        }
    }
}

// ---------------- batched LayerNorm over last dim (768) ----------------
__global__ void ln_kernel(const float* __restrict__ x,
                          const float* __restrict__ g1, const float* __restrict__ b1,
                          const float* __restrict__ g2, const float* __restrict__ b2,
                          float* __restrict__ out) {
    int row = blockIdx.x, tid = threadIdx.x;
    const float* gg = (row < Bz * S) ? g1 : g2;
    const float* bb = (row < Bz * S) ? b1 : b2;
    const float* xr = x + (size_t)row * D;
    float v0 = xr[tid], v1 = xr[tid + 256], v2 = xr[tid + 512];
    float s = v0 + v1 + v2;
    __shared__ float red[8];
    #pragma unroll
    for (int o = 16; o; o >>= 1) s += __shfl_xor_sync(0xffffffffu, s, o);
    if ((tid & 31) == 0) red[tid >> 5] = s;
    __syncthreads();
    float tot = 0.f;
    #pragma unroll
    for (int i = 0; i < 8; i++) tot += red[i];
    float mu = tot * (1.0f / 768.0f);
    float d0 = v0 - mu, d1 = v1 - mu, d2 = v2 - mu;
    float q = d0 * d0 + d1 * d1 + d2 * d2;
    #pragma unroll
    for (int o = 16; o; o >>= 1) q += __shfl_xor_sync(0xffffffffu, q, o);
    __syncthreads();
    if ((tid & 31) == 0) red[tid >> 5] = q;
    __syncthreads();
    float var = 0.f;
    #pragma unroll
    for (int i = 0; i < 8; i++) var += red[i];
    var *= (1.0f / 768.0f);
    float rs = rsqrtf(var + 1e-5f);
    float* orow = out + (size_t)row * D;
    orow[tid]       = d0 * rs * gg[tid]       + bb[tid];
    orow[tid + 256] = d1 * rs * gg[tid + 256] + bb[tid + 256];
    orow[tid + 512] = d2 * rs * gg[tid + 512] + bb[tid + 512];
}

// ---------------- launch ----------------
extern "C" void kernel_launch(void* const* d_in, const int* in_sizes, int n_in,
                              void* d_out, int out_size) {
    const float* pro1 = (const float*)d_in[0];
    const float* pro2 = (const float*)d_in[1];
    const void*  mask = d_in[2];
    const float* W_Q  = (const float*)d_in[3];
    const float* W_K  = (const float*)d_in[4];
    const float* fc1  = (const float*)d_in[5];
    const float* g1   = (const float*)d_in[6];
    const float* b1   = (const float*)d_in[7];
    const float* g2   = (const float*)d_in[8];
    const float* b2   = (const float*)d_in[9];
    float* out = (float*)d_out;

    float *Qp, *Kp, *QTp, *KTp, *CX, *Tp, *CP, *RI, *CI;
    __half* Pp;
    cudaGetSymbolAddress((void**)&Qp, g_Q);
    cudaGetSymbolAddress((void**)&Kp, g_K);
    cudaGetSymbolAddress((void**)&QTp, g_QT);
    cudaGetSymbolAddress((void**)&KTp, g_KT);
    cudaGetSymbolAddress((void**)&Pp, g_P);
    cudaGetSymbolAddress((void**)&CX, g_ctx);
    cudaGetSymbolAddress((void**)&Tp, g_t);
    cudaGetSymbolAddress((void**)&CP, g_cpart);
    cudaGetSymbolAddress((void**)&RI, g_rinv);
    cudaGetSymbolAddress((void**)&CI, g_cinv);

    detect_mask_kernel<<<1, 256>>>((const unsigned int*)mask);

    dim3 gProj(6, 32);
    mm128_kernel<<<gProj, 256>>>(pro1, W_Q, Qp);
    mm128_kernel<<<gProj, 256>>>(pro2, W_K, Kp);

    tr_kernel<<<dim3(32, 2, BH), dim3(32, 8)>>>(Qp, QTp);
    tr_kernel<<<dim3(32, 2, BH), dim3(32, 8)>>>(Kp, KTp);

    scoresT_kernel<<<dim3(8, 8, BH), 256>>>(Kp, QTp, mask, Pp);

    sums_kernel<<<dim3(8, BH), 256>>>(Pp, CP, CI);
    rinv_kernel<<<dim3(4, BH), 256>>>(CP, RI);

    ctx1_kernel<<<dim3(4, BH), 256>>>(KTp, Pp, RI, CX);
    ctx2_kernel<<<dim3(4, BH), 256>>>(Pp, Qp, CI, CX + (size_t)Bz * S * D);

    mm128_kernel<<<dim3(6, 64), 256>>>(CX, fc1, Tp);

    ln_kernel<<<2 * Bz * S, 256>>>(Tp, g1, b1, g2, b2, out);
}

// round 5
// speedup vs baseline: 1.0220x; 1.0152x over previous
#include <cuda_runtime.h>
#include <cuda_fp16.h>
#include <cstdint>

#define Bz 4
#define S 1024
#define D 768
#define H 12
#define DK 64
#define BH (Bz*H)

// ---------------- scratch (device globals) ----------------
__device__ float  g_Q[Bz*S*D];
__device__ float  g_K[Bz*S*D];
__device__ float  g_QT[BH*DK*S];            // fp32, for scoresT B operand
__device__ __half g_QTh[BH*DK*S];           // fp16, ctx2 B operand
__device__ __half g_KTh[BH*DK*S];           // fp16, ctx1 B operand
__device__ __half g_P [(size_t)BH*S*S];     // P[bh][t][s] = exp(score), 0 if masked
__device__ __half g_PT[(size_t)BH*S*S];     // P^T[bh][s][t]
__device__ float  g_ctx[2*Bz*S*D];          // ctx1 | ctx2
__device__ float  g_t[2*Bz*S*D];
__device__ float  g_cpr[BH*8*S];            // partial sums over t (per s), per t-tile
__device__ float  g_cpc[BH*8*S];            // partial sums over s (per t), per s-tile
__device__ float  g_rinv[BH*S];             // 1/sum over t (per s) -> ctx1
__device__ float  g_cinv[BH*S];             // 1/sum over s (per t) -> ctx2
__device__ int    g_mask_mode;              // 0=i32, 1=u8, 2=f32

// ---------------- helpers ----------------
__device__ __forceinline__ unsigned tf32c(float x) {
    unsigned u; asm("cvt.rna.tf32.f32 %0, %1;" : "=r"(u) : "f"(x)); return u;
}
__device__ __forceinline__ void mma8(float c[4], const unsigned a[4], const unsigned b[2]) {
    asm volatile(
        "mma.sync.aligned.m16n8k8.row.col.f32.tf32.tf32.f32 "
        "{%0,%1,%2,%3},{%4,%5,%6,%7},{%8,%9},{%0,%1,%2,%3};\n"
        : "+f"(c[0]), "+f"(c[1]), "+f"(c[2]), "+f"(c[3])
        : "r"(a[0]), "r"(a[1]), "r"(a[2]), "r"(a[3]), "r"(b[0]), "r"(b[1]));
}
__device__ __forceinline__ void hmma16(float c[4], const unsigned a[4], const unsigned b[2]) {
    asm volatile(
        "mma.sync.aligned.m16n8k16.row.col.f32.f16.f16.f32 "
        "{%0,%1,%2,%3},{%4,%5,%6,%7},{%8,%9},{%0,%1,%2,%3};\n"
        : "+f"(c[0]), "+f"(c[1]), "+f"(c[2]), "+f"(c[3])
        : "r"(a[0]), "r"(a[1]), "r"(a[2]), "r"(a[3]), "r"(b[0]), "r"(b[1]));
}
__device__ __forceinline__ int kperm(int k) {
    return (k & ~7) + 2 * (k & 3) + ((k & 7) >> 2);
}

// ---------------- mask dtype sniffer ----------------
__global__ void detect_mask_kernel(const unsigned int* __restrict__ w) {
    __shared__ int s01, sf;
    if (threadIdx.x == 0) { s01 = 1; sf = 1; }
    __syncthreads();
    int a01 = 1, af = 1;
    for (int i = threadIdx.x; i < 4096; i += 256) {
        unsigned v = w[i];
        if (v != 0u && v != 1u) a01 = 0;
        if (v != 0u && v != 0x3F800000u) af = 0;
    }
    if (!a01) atomicAnd(&s01, 0);
    if (!af)  atomicAnd(&sf, 0);
    __syncthreads();
    if (threadIdx.x == 0) g_mask_mode = s01 ? 0 : (sf ? 2 : 1);
}

// ---------------- tf32 GEMM 128x128x32 ----------------
__global__ void __launch_bounds__(256) mm128_kernel(const float* __restrict__ A,
                                                    const float* __restrict__ B,
                                                    float* __restrict__ C) {
    __shared__ unsigned As[128 * 36];
    __shared__ unsigned Bs[32 * 132];
    const int m0 = blockIdx.y * 128, n0 = blockIdx.x * 128;
    const int tid = threadIdx.x, lane = tid & 31, w = tid >> 5;
    const int g = lane >> 2, tq = lane & 3;
    const int mw = (w & 1) * 64, nw = (w >> 1) * 32;
    float c[16][4] = {};
    for (int k0 = 0; k0 < 768; k0 += 32) {
        {
            int kq = tid & 7, kc = kq * 4, bkp = (kq >> 1) * 8 + (kq & 1);
            #pragma unroll
            for (int it = 0; it < 4; it++) {
                int m = (tid >> 3) + it * 32;
                float4 v = *(const float4*)(A + (size_t)(m0 + m) * 768 + k0 + kc);
                unsigned* dst = &As[m * 36 + bkp];
                dst[0] = tf32c(v.x); dst[2] = tf32c(v.y); dst[4] = tf32c(v.z); dst[6] = tf32c(v.w);
            }
        }
        {
            #pragma unroll
            for (int it = 0; it < 4; it++) {
                int kr = (tid >> 5) + it * 8;
                int nc = lane * 4;
                float4 v = *(const float4*)(B + (size_t)(k0 + kr) * 768 + n0 + nc);
                uint4 u; u.x = tf32c(v.x); u.y = tf32c(v.y); u.z = tf32c(v.z); u.w = tf32c(v.w);
                *(uint4*)&Bs[kperm(kr) * 132 + nc] = u;
            }
        }
        __syncthreads();
        #pragma unroll
        for (int ks = 0; ks < 4; ks++) {
            unsigned a[4][4], bf[4][2];
            #pragma unroll
            for (int i = 0; i < 4; i++) {
                int r = mw + 16 * i + g;
                uint2 x = *(const uint2*)&As[r * 36 + ks * 8 + 2 * tq];
                uint2 y = *(const uint2*)&As[(r + 8) * 36 + ks * 8 + 2 * tq];
                a[i][0] = x.x; a[i][1] = y.x; a[i][2] = x.y; a[i][3] = y.y;
            }
            #pragma unroll
            for (int j = 0; j < 4; j++) {
                int col = nw + 8 * j + g;
                bf[j][0] = Bs[(ks * 8 + 2 * tq) * 132 + col];
                bf[j][1] = Bs[(ks * 8 + 2 * tq + 1) * 132 + col];
            }
            #pragma unroll
            for (int i = 0; i < 4; i++)
                #pragma unroll
                for (int j = 0; j < 4; j++) mma8(c[i * 4 + j], a[i], bf[j]);
        }
        __syncthreads();
    }
    #pragma unroll
    for (int i = 0; i < 4; i++) {
        int r = m0 + mw + 16 * i + g;
        #pragma unroll
        for (int j = 0; j < 4; j++) {
            int col = n0 + nw + 8 * j + 2 * tq;
            *(float2*)(C + (size_t)r * 768 + col)       = make_float2(c[i*4+j][0], c[i*4+j][1]);
            *(float2*)(C + (size_t)(r + 8) * 768 + col) = make_float2(c[i*4+j][2], c[i*4+j][3]);
        }
    }
}

// ---------------- head transpose: X[b][s][h*64+d] -> XT fp32 + XTh fp16 ----------------
__global__ void tr_kernel(const float* __restrict__ X, float* __restrict__ XT,
                          __half* __restrict__ XTh) {
    __shared__ float tile[32][33];
    int bh = blockIdx.z, b = bh / H, h = bh % H;
    int s0 = blockIdx.x * 32, d0 = blockIdx.y * 32;
    int tx = threadIdx.x, ty = threadIdx.y;
    #pragma unroll
    for (int i = 0; i < 4; i++)
        tile[ty + 8 * i][tx] = X[(size_t)(b * S + s0 + ty + 8 * i) * D + h * DK + d0 + tx];
    __syncthreads();
    #pragma unroll
    for (int i = 0; i < 4; i++) {
        float v = tile[tx][ty + 8 * i];
        size_t idx = (size_t)(bh * DK + d0 + ty + 8 * i) * S + s0 + tx;
        XT[idx]  = v;
        XTh[idx] = __float2half_rn(v);
    }
}

// ---------------- scoresT: P, PT fp16 + partial sums, all from one tile ----------------
__global__ void __launch_bounds__(256) scoresT_kernel(const float* __restrict__ Kmat,
                                                      const float* __restrict__ QT,
                                                      const void* __restrict__ mask,
                                                      __half* __restrict__ P,
                                                      __half* __restrict__ PT,
                                                      float* __restrict__ cpr,
                                                      float* __restrict__ cpc) {
    __shared__ union SU {
        struct { unsigned As[128 * 36]; unsigned Bs[32 * 132]; } g;
        __half Ps[128 * 136];   // [t][s], stride 136 halfs (68 words)
    } su;
    unsigned* As = su.g.As;
    unsigned* Bs = su.g.Bs;
    const int bh = blockIdx.z, b = bh / H, h = bh % H;
    const int s0 = blockIdx.x * 128, t0 = blockIdx.y * 128;
    const float* Ag = Kmat + (size_t)(b * S + t0) * D + h * DK;
    const float* Bg = QT + (size_t)bh * DK * S + s0;
    const int tid = threadIdx.x, lane = tid & 31, w = tid >> 5;
    const int g = lane >> 2, tq = lane & 3;
    const int mw = (w & 1) * 64, nw = (w >> 1) * 32;
    float c[16][4] = {};
    #pragma unroll
    for (int k0 = 0; k0 < 64; k0 += 32) {
        {
            int kq = tid & 7, kc = kq * 4, bkp = (kq >> 1) * 8 + (kq & 1);
            #pragma unroll
            for (int it = 0; it < 4; it++) {
                int m = (tid >> 3) + it * 32;
                float4 v = *(const float4*)(Ag + (size_t)m * D + k0 + kc);
                unsigned* dst = &As[m * 36 + bkp];
                dst[0] = tf32c(v.x); dst[2] = tf32c(v.y); dst[4] = tf32c(v.z); dst[6] = tf32c(v.w);
            }
        }
        {
            #pragma unroll
            for (int it = 0; it < 4; it++) {
                int kr = (tid >> 5) + it * 8;
                int nc = lane * 4;
                float4 v = *(const float4*)(Bg + (size_t)(k0 + kr) * S + nc);
                uint4 u; u.x = tf32c(v.x); u.y = tf32c(v.y); u.z = tf32c(v.z); u.w = tf32c(v.w);
                *(uint4*)&Bs[kperm(kr) * 132 + nc] = u;
            }
        }
        __syncthreads();
        #pragma unroll
        for (int ks = 0; ks < 4; ks++) {
            unsigned a[4][4], bf[4][2];
            #pragma unroll
            for (int i = 0; i < 4; i++) {
                int r = mw + 16 * i + g;
                uint2 x = *(const uint2*)&As[r * 36 + ks * 8 + 2 * tq];
                uint2 y = *(const uint2*)&As[(r + 8) * 36 + ks * 8 + 2 * tq];
                a[i][0] = x.x; a[i][1] = y.x; a[i][2] = x.y; a[i][3] = y.y;
            }
            #pragma unroll
            for (int j = 0; j < 4; j++) {
                int col = nw + 8 * j + g;
                bf[j][0] = Bs[(ks * 8 + 2 * tq) * 132 + col];
                bf[j][1] = Bs[(ks * 8 + 2 * tq + 1) * 132 + col];
            }
            #pragma unroll
            for (int i = 0; i < 4; i++)
                #pragma unroll
                for (int j = 0; j < 4; j++) mma8(c[i * 4 + j], a[i], bf[j]);
        }
        __syncthreads();
    }
    // mask + exp, stage P tile into smem as fp16
    const int mode = g_mask_mode;
    const int* m32 = (const int*)mask;
    const unsigned char* m8 = (const unsigned char*)mask;
    const float* mf = (const float*)mask;
    #pragma unroll
    for (int i = 0; i < 4; i++) {
        int tl = mw + 16 * i + g;
        int rA = t0 + tl;
        #pragma unroll
        for (int j = 0; j < 4; j++) {
            int sl = nw + 8 * j + 2 * tq;
            int cs = s0 + sl;
            float* cc = c[i * 4 + j];
            size_t iA = ((size_t)bh * S + rA) * S + cs;
            size_t iB = iA + (size_t)8 * S;
            bool k0m, k1m, k2m, k3m;
            if (mode == 0) {
                int2 qa = *(const int2*)(m32 + iA); int2 qb = *(const int2*)(m32 + iB);
                k0m = qa.x != 0; k1m = qa.y != 0; k2m = qb.x != 0; k3m = qb.y != 0;
            } else if (mode == 1) {
                uchar2 qa = *(const uchar2*)(m8 + iA); uchar2 qb = *(const uchar2*)(m8 + iB);
                k0m = qa.x != 0; k1m = qa.y != 0; k2m = qb.x != 0; k3m = qb.y != 0;
            } else {
                float2 qa = *(const float2*)(mf + iA); float2 qb = *(const float2*)(mf + iB);
                k0m = qa.x != 0.0f; k1m = qa.y != 0.0f; k2m = qb.x != 0.0f; k3m = qb.y != 0.0f;
            }
            float p0 = k0m ? 0.0f : __expf(0.125f * cc[0]);
            float p1 = k1m ? 0.0f : __expf(0.125f * cc[1]);
            float p2 = k2m ? 0.0f : __expf(0.125f * cc[2]);
            float p3 = k3m ? 0.0f : __expf(0.125f * cc[3]);
            *(__half2*)&su.Ps[(size_t)tl * 136 + sl]       = __floats2half2_rn(p0, p1);
            *(__half2*)&su.Ps[(size_t)(tl + 8) * 136 + sl] = __floats2half2_rn(p2, p3);
        }
    }
    __syncthreads();
    // partial sums (deterministic, serial per thread)
    if (tid < 128) {
        // sum over s within tile -> per-t partial (for cinv)
        float rs = 0.f;
        const __half2* row = (const __half2*)&su.Ps[(size_t)tid * 136];
        #pragma unroll 16
        for (int j = 0; j < 64; j++) {
            float2 f = __half22float2(row[j]);
            rs += f.x + f.y;
        }
        cpc[((size_t)bh * 8 + blockIdx.x) * S + t0 + tid] = rs;
        // sum over t within tile -> per-s partial (for rinv)
        float csum = 0.f;
        #pragma unroll 16
        for (int r = 0; r < 128; r++) csum += __half2float(su.Ps[(size_t)r * 136 + tid]);
        cpr[((size_t)bh * 8 + blockIdx.y) * S + s0 + tid] = csum;
    }
    __syncthreads();
    // write P[t][s] from smem (coalesced)
    #pragma unroll
    for (int it = 0; it < 32; it++) {
        int t = it * 4 + (tid >> 6);
        int sp = tid & 63;
        __half2 v = *(const __half2*)&su.Ps[(size_t)t * 136 + 2 * sp];
        *(__half2*)(P + ((size_t)bh * S + t0 + t) * S + s0 + 2 * sp) = v;
    }
    // write PT[s][t] from smem (coalesced gmem; strided smem)
    #pragma unroll
    for (int it = 0; it < 32; it++) {
        int s = it * 4 + (tid >> 6);
        int tp = tid & 63;
        __half h0 = su.Ps[(size_t)(2 * tp) * 136 + s];
        __half h1 = su.Ps[(size_t)(2 * tp + 1) * 136 + s];
        *(__half2*)(PT + ((size_t)bh * S + s0 + s) * S + t0 + 2 * tp) = __halves2half2(h0, h1);
    }
}

// ---------------- reduce partials -> rinv, cinv ----------------
__global__ void rcinv_kernel(const float* __restrict__ cpr, const float* __restrict__ cpc,
                             float* __restrict__ rinv, float* __restrict__ cinv) {
    int bh = blockIdx.y;
    int x = blockIdx.x * 256 + threadIdx.x;
    float sr = 0.f, sc = 0.f;
    #pragma unroll
    for (int j = 0; j < 8; j++) {
        sr += cpr[((size_t)bh * 8 + j) * S + x];
        sc += cpc[((size_t)bh * 8 + j) * S + x];
    }
    rinv[bh * S + x] = 1.0f / sr;
    cinv[bh * S + x] = 1.0f / sc;
}

// ---------------- ctx (fp16 HMMA): C[m][d] = minv[m] * sum_k A[m][k] * XT[d][k] ----------------
// ctx1: A=PT (m=s,k=t), XT=KTh, minv=rinv.  ctx2: A=P (m=t,k=s), XT=QTh, minv=cinv.
__global__ void __launch_bounds__(256) ctxh_kernel(const __half* __restrict__ A,
                                                   const __half* __restrict__ XTh,
                                                   const float* __restrict__ minv,
                                                   float* __restrict__ C) {
    __shared__ unsigned Ah[256 * 20];  // [m][kpair], stride 20 words (16 pairs + pad)
    __shared__ unsigned Bh[64 * 20];   // [d][kpair]
    __shared__ float mv[256];
    const int bh = blockIdx.y, b = bh / H, h = bh % H;
    const int m0 = blockIdx.x * 256;
    const __half* Ag = A + ((size_t)bh * S + m0) * S;
    const __half* Bg = XTh + (size_t)bh * DK * S;
    const int tid = threadIdx.x, lane = tid & 31, w = tid >> 5;
    const int g = lane >> 2, tq = lane & 3;
    const int mw = (w >> 1) * 64, nw = (w & 1) * 32;
    mv[tid] = minv[bh * S + m0 + tid];
    const int lrow = tid >> 2, lpart = tid & 3;
    float c[16][4] = {};
    for (int k0 = 0; k0 < S; k0 += 32) {
        #pragma unroll
        for (int it = 0; it < 4; it++) {
            int m = it * 64 + lrow;
            uint4 v = *(const uint4*)(Ag + (size_t)m * S + k0 + lpart * 8);
            *(uint4*)&Ah[m * 20 + lpart * 4] = v;
        }
        {
            int d = tid >> 2;
            uint4 v = *(const uint4*)(Bg + (size_t)d * S + k0 + lpart * 8);
            *(uint4*)&Bh[d * 20 + lpart * 4] = v;
        }
        __syncthreads();
        #pragma unroll
        for (int ks = 0; ks < 2; ks++) {
            unsigned a[4][4], bf[4][2];
            #pragma unroll
            for (int i = 0; i < 4; i++) {
                int r = mw + 16 * i + g;
                a[i][0] = Ah[r * 20 + 8 * ks + tq];
                a[i][1] = Ah[(r + 8) * 20 + 8 * ks + tq];
                a[i][2] = Ah[r * 20 + 8 * ks + tq + 4];
                a[i][3] = Ah[(r + 8) * 20 + 8 * ks + tq + 4];
            }
            #pragma unroll
            for (int j = 0; j < 4; j++) {
                int col = nw + 8 * j + g;
                bf[j][0] = Bh[col * 20 + 8 * ks + tq];
                bf[j][1] = Bh[col * 20 + 8 * ks + tq + 4];
            }
            #pragma unroll
            for (int i = 0; i < 4; i++)
                #pragma unroll
                for (int j = 0; j < 4; j++) hmma16(c[i * 4 + j], a[i], bf[j]);
        }
        __syncthreads();
    }
    #pragma unroll
    for (int i = 0; i < 4; i++) {
        int rl = mw + 16 * i + g;
        float s0v = mv[rl], s1v = mv[rl + 8];
        #pragma unroll
        for (int j = 0; j < 4; j++) {
            int dcol = nw + 8 * j + 2 * tq;
            float* cc = c[i * 4 + j];
            size_t a0 = (size_t)(b * S + m0 + rl) * D + h * DK + dcol;
            *(float2*)(C + a0)                 = make_float2(cc[0] * s0v, cc[1] * s0v);
            *(float2*)(C + a0 + (size_t)8 * D) = make_float2(cc[2] * s1v, cc[3] * s1v);
        }
    }
}

// ---------------- batched LayerNorm over last dim (768) ----------------
__global__ void ln_kernel(const float* __restrict__ x,
                          const float* __restrict__ g1, const float* __restrict__ b1,
                          const float* __restrict__ g2, const float* __restrict__ b2,
                          float* __restrict__ out) {
    int row = blockIdx.x, tid = threadIdx.x;
    const float* gg = (row < Bz * S) ? g1 : g2;
    const float* bb = (row < Bz * S) ? b1 : b2;
    const float* xr = x + (size_t)row * D;
    float v0 = xr[tid], v1 = xr[tid + 256], v2 = xr[tid + 512];
    float s = v0 + v1 + v2;
    __shared__ float red[8];
    #pragma unroll
    for (int o = 16; o; o >>= 1) s += __shfl_xor_sync(0xffffffffu, s, o);
    if ((tid & 31) == 0) red[tid >> 5] = s;
    __syncthreads();
    float tot = 0.f;
    #pragma unroll
    for (int i = 0; i < 8; i++) tot += red[i];
    float mu = tot * (1.0f / 768.0f);
    float d0 = v0 - mu, d1 = v1 - mu, d2 = v2 - mu;
    float q = d0 * d0 + d1 * d1 + d2 * d2;
    #pragma unroll
    for (int o = 16; o; o >>= 1) q += __shfl_xor_sync(0xffffffffu, q, o);
    __syncthreads();
    if ((tid & 31) == 0) red[tid >> 5] = q;
    __syncthreads();
    float var = 0.f;
    #pragma unroll
    for (int i = 0; i < 8; i++) var += red[i];
    var *= (1.0f / 768.0f);
    float rs = rsqrtf(var + 1e-5f);
    float* orow = out + (size_t)row * D;
    orow[tid]       = d0 * rs * gg[tid]       + bb[tid];
    orow[tid + 256] = d1 * rs * gg[tid + 256] + bb[tid + 256];
    orow[tid + 512] = d2 * rs * gg[tid + 512] + bb[tid + 512];
}

// ---------------- launch ----------------
extern "C" void kernel_launch(void* const* d_in, const int* in_sizes, int n_in,
                              void* d_out, int out_size) {
    const float* pro1 = (const float*)d_in[0];
    const float* pro2 = (const float*)d_in[1];
    const void*  mask = d_in[2];
    const float* W_Q  = (const float*)d_in[3];
    const float* W_K  = (const float*)d_in[4];
    const float* fc1  = (const float*)d_in[5];
    const float* g1   = (const float*)d_in[6];
    const float* b1   = (const float*)d_in[7];
    const float* g2   = (const float*)d_in[8];
    const float* b2   = (const float*)d_in[9];
    float* out = (float*)d_out;

    float *Qp, *Kp, *QTp, *CX, *Tp, *CPR, *CPC, *RI, *CI;
    __half *QTh, *KTh, *Pp, *PTp;
    cudaGetSymbolAddress((void**)&Qp, g_Q);
    cudaGetSymbolAddress((void**)&Kp, g_K);
    cudaGetSymbolAddress((void**)&QTp, g_QT);
    cudaGetSymbolAddress((void**)&QTh, g_QTh);
    cudaGetSymbolAddress((void**)&KTh, g_KTh);
    cudaGetSymbolAddress((void**)&Pp, g_P);
    cudaGetSymbolAddress((void**)&PTp, g_PT);
    cudaGetSymbolAddress((void**)&CX, g_ctx);
    cudaGetSymbolAddress((void**)&Tp, g_t);
    cudaGetSymbolAddress((void**)&CPR, g_cpr);
    cudaGetSymbolAddress((void**)&CPC, g_cpc);
    cudaGetSymbolAddress((void**)&RI, g_rinv);
    cudaGetSymbolAddress((void**)&CI, g_cinv);

    detect_mask_kernel<<<1, 256>>>((const unsigned int*)mask);

    dim3 gProj(6, 32);
    mm128_kernel<<<gProj, 256>>>(pro1, W_Q, Qp);
    mm128_kernel<<<gProj, 256>>>(pro2, W_K, Kp);

    // QT fp32 (scores) + QTh fp16 (ctx2 B); KTh fp16 (ctx1 B) — K fp32 XT reuses QT buffer? No: separate unused.
    tr_kernel<<<dim3(32, 2, BH), dim3(32, 8)>>>(Qp, QTp, QTh);
    // For K we only need the fp16 transpose; fp32 goes to a scratch region (g_t reused pre-output).
    tr_kernel<<<dim3(32, 2, BH), dim3(32, 8)>>>(Kp, Tp, KTh);

    scoresT_kernel<<<dim3(8, 8, BH), 256>>>(Kp, QTp, mask, Pp, PTp, CPR, CPC);

    rcinv_kernel<<<dim3(4, BH), 256>>>(CPR, CPC, RI, CI);

    ctxh_kernel<<<dim3(4, BH), 256>>>(PTp, KTh, RI, CX);                       // ctx1
    ctxh_kernel<<<dim3(4, BH), 256>>>(Pp, QTh, CI, CX + (size_t)Bz * S * D);   // ctx2

    mm128_kernel<<<dim3(6, 64), 256>>>(CX, fc1, Tp);

    ln_kernel<<<2 * Bz * S, 256>>>(Tp, g1, b1, g2, b2, out);
}